// round 3
// baseline (speedup 1.0000x reference)
#include <cuda_runtime.h>
#include <cstdint>

#define NCOUNT 8
#define B_TOTAL 16384
#define L1 3072
#define M_TILE 128
#define KCHUNK 64
#define NCHUNK (L1 / KCHUNK)               // 48
#define NSTAGE 4
#define MAX_TILES (B_TOTAL / M_TILE + NCOUNT)  // 136
#define NTHREADS 256

// ---------------- device scratch ----------------
__device__ int   g_fill[NCOUNT];
__device__ int   g_rows2[NCOUNT][B_TOTAL];      // per-bucket row lists (not packed)
__device__ float g_wcomb[NCOUNT * 16 * L1];     // combined l1_w[bucket]+l1f_w

#define FMA2(d, a, b) asm("fma.rn.f32x2 %0, %1, %2, %0;" : "+l"(d) : "l"(a), "l"(b))

// ---------------- prep 1: zero fills + combined weights ----------------
__global__ void k_pre(const float* __restrict__ l1w, const float* __restrict__ l1fw) {
    int e = blockIdx.x * blockDim.x + threadIdx.x;
    if (blockIdx.x == 0 && threadIdx.x < NCOUNT) g_fill[threadIdx.x] = 0;
    if (e < NCOUNT * 16 * L1) {
        int k = e % L1;
        int r = (e / L1) % 16;
        g_wcomb[e] = l1w[e] + l1fw[r * L1 + k];
    }
}

// ---------------- prep 2: bucket scatter (block-aggregated atomics) ----------------
__global__ void k_scatter(const int* __restrict__ idx) {
    __shared__ int s_cnt[NCOUNT];
    __shared__ int s_base[NCOUNT];
    int tid = threadIdx.x;
    int i = blockIdx.x * blockDim.x + tid;
    int lane = tid & 31;
    if (tid < NCOUNT) s_cnt[tid] = 0;
    __syncthreads();
    int c = idx[i];
    unsigned mask = __match_any_sync(0xffffffffu, c);
    int leader = __ffs(mask) - 1;
    int rank = __popc(mask & ((1u << lane) - 1u));
    int wbase = 0;
    if (lane == leader) wbase = atomicAdd(&s_cnt[c], __popc(mask));
    wbase = __shfl_sync(mask, wbase, leader);
    __syncthreads();
    if (tid < NCOUNT) s_base[tid] = s_cnt[tid] ? atomicAdd(&g_fill[tid], s_cnt[tid]) : 0;
    __syncthreads();
    g_rows2[c][s_base[c] + wbase + rank] = i;
}

// ---------------- main fused kernel ----------------
// dyn smem: sx[4][128][16] float4 = 128 KB, then sw[4][16][16] float4 = 16 KB
extern __shared__ float4 s_dyn[];

__global__ void __launch_bounds__(NTHREADS, 1)
k_main(const float* __restrict__ x,
       const float* __restrict__ l1b, const float* __restrict__ l1fb,
       const float* __restrict__ l2w, const float* __restrict__ l2b,
       const float* __restrict__ outw, const float* __restrict__ outb,
       float* __restrict__ out)
{
    const int tid = threadIdx.x;

    // ---- derive tile -> (bucket, start, rows) from bucket counts ----
    int bucket = -1, startrow = 0, rows = 0;
    {
        int t = blockIdx.x;
#pragma unroll
        for (int c = 0; c < NCOUNT; c++) {
            int n = __ldg(&g_fill[c]);
            int nt = (n + M_TILE - 1) / M_TILE;
            if (bucket < 0) {
                if (t < nt) {
                    bucket = c;
                    startrow = t * M_TILE;
                    rows = n - startrow; if (rows > M_TILE) rows = M_TILE;
                } else t -= nt;
            }
        }
    }
    if (bucket < 0) return;

    __shared__ int   s_rows[M_TILE];
    __shared__ float s_wpad[32 * 32];
    __shared__ float s_outw[32];
    __shared__ float s_l2b[32];
    __shared__ float s_bc[16];
    __shared__ float s_outb;

    if (tid < M_TILE) {
        int mi = tid < rows ? tid : rows - 1;
        s_rows[tid] = g_rows2[bucket][startrow + mi];
    }
#pragma unroll
    for (int i = 0; i < 4; i++) {
        int e = tid + NTHREADS * i;
        int o = e >> 5, j = e & 31;
        s_wpad[e] = (j < 30) ? l2w[(bucket * 32 + o) * 30 + j] : 0.f;
    }
    if (tid < 32) {
        s_outw[tid] = outw[bucket * 32 + tid];
        s_l2b[tid]  = l2b[bucket * 32 + tid];
    }
    if (tid < 16) s_bc[tid] = l1b[bucket * 16 + tid] + l1fb[tid];
    if (tid == 0) s_outb = outb[bucket];
    __syncthreads();

    float4* sx = s_dyn;            // 4 * 2048 float4 = 128 KB
    float4* sw = s_dyn + 8192;     // 4 * 256  float4 = 16 KB

    unsigned sx0 = (unsigned)__cvta_generic_to_shared(sx);
    unsigned sw0 = (unsigned)__cvta_generic_to_shared(sw);

    // loader assignment: kkl = float4-in-row (0..15), mb = row base (0..15)
    const int kkl = tid & 15;
    const int mb  = tid >> 4;

    // per-thread x source pointers (8 rows) and store offsets
    const float* xsrc[8];
    unsigned     xdst[8];
#pragma unroll
    for (int i = 0; i < 8; i++) {
        int m = mb + 16 * i;
        xsrc[i] = x + (size_t)s_rows[m] * L1 + kkl * 4;
        xdst[i] = (unsigned)((m * 16 + (kkl ^ (m >> 3))) * 16);
    }
    const float* wsrc = g_wcomb + (size_t)(bucket * 16 + (tid >> 4)) * L1 + (tid & 15) * 4;
    const unsigned wdst = (unsigned)(((tid >> 4) * 16 + (tid & 15)) * 16);

    // compute assignment
    const int ks = tid >> 5;           // k-split warp 0..7 (2 float4 each)
    const int ng = (tid >> 4) & 1;
    const int mg = tid & 15;
    const int m0 = mg * 8;
    const int j0 = ng * 8;

    unsigned long long acc[8][8];
#pragma unroll
    for (int r = 0; r < 8; r++)
#pragma unroll
        for (int s = 0; s < 8; s++) acc[r][s] = 0ull;

#define ISSUE_CHUNK(cc)                                                                \
    do {                                                                               \
        int k0_ = (cc) * KCHUNK;                                                       \
        int bb_ = (cc) & (NSTAGE - 1);                                                 \
        unsigned sxb_ = sx0 + (unsigned)bb_ * 2048u * 16u;                             \
        _Pragma("unroll")                                                              \
        for (int i_ = 0; i_ < 8; i_++) {                                               \
            asm volatile("cp.async.cg.shared.global [%0], [%1], 16;\n"                 \
                         :: "r"(sxb_ + xdst[i_]), "l"(xsrc[i_] + k0_));                \
        }                                                                              \
        unsigned swb_ = sw0 + (unsigned)bb_ * 256u * 16u;                              \
        asm volatile("cp.async.cg.shared.global [%0], [%1], 16;\n"                     \
                     :: "r"(swb_ + wdst), "l"(wsrc + k0_));                            \
        asm volatile("cp.async.commit_group;\n");                                      \
    } while (0)

    ISSUE_CHUNK(0);
    ISSUE_CHUNK(1);
    ISSUE_CHUNK(2);

#pragma unroll 1
    for (int c = 0; c < NCHUNK; c++) {
        if (c + 2 <= NCHUNK - 1)      asm volatile("cp.async.wait_group 2;\n");
        else if (c + 1 <= NCHUNK - 1) asm volatile("cp.async.wait_group 1;\n");
        else                          asm volatile("cp.async.wait_group 0;\n");
        __syncthreads();
        if (c + 3 < NCHUNK) ISSUE_CHUNK(c + 3);

        const ulonglong2* xb = (const ulonglong2*)(sx + (c & (NSTAGE - 1)) * 2048);
        const ulonglong2* wb = (const ulonglong2*)(sw + (c & (NSTAGE - 1)) * 256);

#pragma unroll
        for (int i = 0; i < 2; i++) {
            int k4 = ks * 2 + i;                 // 0..15 across warps
            ulonglong2 wv[8];
#pragma unroll
            for (int s = 0; s < 8; s++) wv[s] = wb[(j0 + s) * 16 + k4];
            int swk = k4 ^ mg;
#pragma unroll
            for (int r = 0; r < 8; r++) {
                ulonglong2 xv = xb[(m0 + r) * 16 + swk];
#pragma unroll
                for (int s = 0; s < 8; s++) {
                    FMA2(acc[r][s], xv.x, wv[s].x);
                    FMA2(acc[r][s], xv.y, wv[s].y);
                }
            }
        }
    }

    // ---- reduce k-split partials via smem (overlay on sx buffers 0/1/2: no
    //      overlap with chunk 47's buffers: x-stage 3 @96-128KB, w @128-144KB) ----
    float* accs = (float*)s_dyn;   // 8 * 128 * 17 floats = 69632 B
#pragma unroll
    for (int r = 0; r < 8; r++)
#pragma unroll
        for (int s = 0; s < 8; s++) {
            union { unsigned long long u; float2 f; } cv;
            cv.u = acc[r][s];
            accs[ks * 2176 + (m0 + r) * 17 + (j0 + s)] = cv.f.x + cv.f.y;
        }
    __syncthreads();

    // ---- fused stage 2/3: one row per thread ----
    if (tid < M_TILE) {
        float t[16];
#pragma unroll
        for (int j = 0; j < 16; j++) {
            float a = 0.f;
#pragma unroll
            for (int p = 0; p < 8; p++) a += accs[p * 2176 + tid * 17 + j];
            t[j] = a + s_bc[j];
        }

        float v[32];
#pragma unroll
        for (int j = 0; j < 15; j++) {
            float a = t[j];
            v[j]      = fminf(a * a * (127.0f / 128.0f), 1.0f);
            v[15 + j] = fminf(fmaxf(a, 0.0f), 1.0f);
        }
        v[30] = 0.f; v[31] = 0.f;

        float res = t[15] + s_outb;
        const float4* wp4 = (const float4*)s_wpad;
#pragma unroll
        for (int o = 0; o < 32; o++) {
            float s = s_l2b[o];
#pragma unroll
            for (int q = 0; q < 8; q++) {
                float4 w = wp4[o * 8 + q];
                s += w.x * v[q * 4] + w.y * v[q * 4 + 1] + w.z * v[q * 4 + 2] + w.w * v[q * 4 + 3];
            }
            s = fminf(fmaxf(s, 0.0f), 1.0f);
            res += s * s_outw[o];
        }

        if (tid < rows) out[s_rows[tid]] = res;
    }
}

// ---------------- launcher ----------------
extern "C" void kernel_launch(void* const* d_in, const int* in_sizes, int n_in,
                              void* d_out, int out_size)
{
    const float* x     = (const float*)d_in[0];
    const int*   idx   = (const int*)  d_in[1];
    const float* l1w   = (const float*)d_in[2];
    const float* l1b   = (const float*)d_in[3];
    const float* l1fw  = (const float*)d_in[4];
    const float* l1fb  = (const float*)d_in[5];
    const float* l2w   = (const float*)d_in[6];
    const float* l2b   = (const float*)d_in[7];
    const float* outw  = (const float*)d_in[8];
    const float* outb  = (const float*)d_in[9];
    float* out = (float*)d_out;

    static bool attr_set = false;
    if (!attr_set) {
        cudaFuncSetAttribute(k_main, cudaFuncAttributeMaxDynamicSharedMemorySize, 147456);
        attr_set = true;
    }

    k_pre<<<(NCOUNT * 16 * L1 + 511) / 512, 512>>>(l1w, l1fw);
    k_scatter<<<B_TOTAL / 512, 512>>>(idx);
    k_main<<<MAX_TILES, NTHREADS, 147456>>>(x, l1b, l1fb, l2w, l2b, outw, outb, out);
}